// round 4
// baseline (speedup 1.0000x reference)
#include <cuda_runtime.h>
#include <math.h>
#include <stdint.h>

#define BB 16
#define NN 2048
#define DD 512
#define TFc 7
#define HH 8
#define TT 96
#define BND 16777216ull   // 16*2048*512

// scratch: 10*BND + small tail
__device__ float g_buf[170066688];

__device__ __forceinline__ float sigm(float x){ return 1.f/(1.f+expf(-x)); }

// ------------------------------------------------------------------ utils
__global__ void copy_k(const float* __restrict__ a, float* __restrict__ b, int n){
    int i = blockIdx.x*256 + threadIdx.x;
    if(i < n) b[i] = a[i];
}

__global__ void copy_lastg_k(const float* __restrict__ lg, float* __restrict__ dst){
    int id = blockIdx.x*256 + threadIdx.x;   // 8192
    int b = id >> 9, d = id & 511;
    dst[id] = lg[(size_t)b*NN*DD + (size_t)(NN-1)*DD + d];
}

// ------------------------------------------------------------------ embed
// z[b,n,d] = sum_{c,k} x[b,n+k-1,c]*w[d,c,k] + eb[d]
__global__ void embed_k(const float* __restrict__ x, const float* __restrict__ w,
                        const float* __restrict__ eb, float* __restrict__ z){
    int d = blockIdx.x*128 + threadIdx.x;
    int n = blockIdx.y, b = blockIdx.z;
    float acc = eb[d];
#pragma unroll
    for(int k=0;k<3;k++){
        int nn = n + k - 1;
        if(nn < 0 || nn >= NN) continue;
        const float* xr = x + ((size_t)b*NN + nn)*TFc;
        const float* wr = w + (size_t)d*21 + k;
#pragma unroll
        for(int c=0;c<TFc;c++) acc += xr[c]*wr[c*3];
    }
    z[((size_t)b*NN + n)*DD + d] = acc;
}

// ------------------------------------------------------------------ freq attention
// one block per (b,d): 2048-pt FFT in smem, top-4 amp threshold, sparse inverse.
__global__ void freqatt_k(float* __restrict__ z, float* __restrict__ ls,
                          int* __restrict__ NKo, int* __restrict__ KFo,
                          float2* __restrict__ KVo){
    __shared__ float2 X[2048];
    __shared__ float2 tw[1024];
    __shared__ float amp2[1025];
    __shared__ float rv[256];
    __shared__ int   ri[256];
    __shared__ int   kept[32];
    __shared__ int   nkept;
    __shared__ float thr_s;

    int d = blockIdx.x, b = blockIdx.y, tid = threadIdx.x;
    float* col = z + (size_t)b*NN*DD + d;

    for(int j=tid;j<1024;j+=256){
        float sa,ca;
        sincosf(-3.14159265358979323846f*(float)j*(1.f/1024.f), &sa, &ca);
        tw[j] = make_float2(ca, sa);
    }
    for(int j=tid;j<2048;j+=256){
        int r = (int)(__brev((unsigned)j) >> 21);
        X[j] = make_float2(col[(size_t)r*DD], 0.f);
    }
    if(tid==0) nkept = 0;
    __syncthreads();

    // 11 radix-2 DIT stages
    for(int s=1;s<=11;s++){
        int half = 1 << (s-1);
        int tsh  = 11 - s;
        for(int k=tid;k<1024;k+=256){
            int j  = k & (half-1);
            int i1 = ((k >> (s-1)) << s) | j;
            int i2 = i1 + half;
            float2 w = tw[j << tsh];
            float2 u = X[i1], v = X[i2];
            float tr = v.x*w.x - v.y*w.y;
            float ti = v.x*w.y + v.y*w.x;
            X[i1] = make_float2(u.x+tr, u.y+ti);
            X[i2] = make_float2(u.x-tr, u.y-ti);
        }
        __syncthreads();
    }

    for(int f=tid;f<=1024;f+=256){
        float2 v = X[f];
        amp2[f] = v.x*v.x + v.y*v.y;
    }
    __syncthreads();

    // 4 argmax rounds -> threshold = 4th largest amp^2
    for(int r=0;r<4;r++){
        float bv = -1.f; int bi = 0;
        for(int f=tid;f<=1024;f+=256){
            float v = amp2[f];
            if(v > bv){ bv = v; bi = f; }
        }
        rv[tid] = bv; ri[tid] = bi;
        __syncthreads();
        for(int st=128;st>0;st>>=1){
            if(tid < st && rv[tid+st] > rv[tid]){ rv[tid]=rv[tid+st]; ri[tid]=ri[tid+st]; }
            __syncthreads();
        }
        if(tid==0){
            if(r < 3){ kept[nkept] = ri[0]; nkept++; amp2[ri[0]] = -2.f; }
            else thr_s = rv[0];
        }
        __syncthreads();
    }
    float thr = thr_s;
    for(int f=tid;f<=1024;f+=256){
        if(amp2[f] >= thr){
            int p = atomicAdd(&nkept, 1);
            if(p < 32) kept[p] = f;
        }
    }
    __syncthreads();
    int nk = min(nkept, 32);
    // deterministic order: insertion sort kept bins (nk is tiny)
    if(tid == 0){
        for(int i=1;i<nk;i++){
            int key = kept[i], j = i-1;
            while(j >= 0 && kept[j] > key){ kept[j+1] = kept[j]; j--; }
            kept[j+1] = key;
        }
    }
    __syncthreads();

    // sparse inverse rFFT, write ls and z -= ls
    float* lcol = ls + (size_t)b*NN*DD + d;
    for(int n=tid;n<2048;n+=256){
        float acc = 0.f;
        for(int q=0;q<nk;q++){
            int f = kept[q];
            float2 Xf = X[f];
            float wq = (f==0 || f==1024) ? 1.f : 2.f;
            int ph = (f*n) & 2047;
            float2 t = tw[ph & 1023];
            float sg = (ph & 1024) ? -1.f : 1.f;
            float ca = sg*t.x, sa = -sg*t.y;      // e^{+i*2*pi*ph/2048}
            acc += wq*(Xf.x*ca - Xf.y*sa);
        }
        acc *= (1.f/2048.f);
        lcol[(size_t)n*DD] = acc;
        col[(size_t)n*DD] -= acc;
    }

    // export kept bins for the final extrapolation
    int ns = min(nk, 16);
    int seq = b*DD + d;
    if(tid==0) NKo[seq] = ns;
    if(tid < ns){
        KFo[seq*16 + tid] = kept[tid];
        KVo[seq*16 + tid] = X[kept[tid]];
    }
}

// ------------------------------------------------------------------ GEMM  C = A@W^T + bias
// A:[M,K] rm, W:[Nn,K] rm. mode 0: store; 1: sigmoid store; 2: store and Z -= C.
__global__ __launch_bounds__(256)
void gemm_k(const float* __restrict__ A, const float* __restrict__ W,
            const float* __restrict__ bias, float* __restrict__ C,
            float* __restrict__ Z, int M, int Nn, int K, int mode){
    __shared__ float As[16][132];
    __shared__ float Bs[16][132];
    int bm = blockIdx.y << 7, bn = blockIdx.x << 7;
    int tid = threadIdx.x;
    int tx = tid & 15, ty = tid >> 4;
    int lr = tid >> 2;            // 0..63
    int lc = (tid & 3) << 2;      // 0,4,8,12
    float acc[8][8];
#pragma unroll
    for(int i=0;i<8;i++)
#pragma unroll
        for(int j=0;j<8;j++) acc[i][j] = 0.f;

    const float* Ap = A + (size_t)(bm+lr)*K + lc;
    const float* Bp = W + (size_t)(bn+lr)*K + lc;
    int ktiles = K >> 4;
    for(int kt=0;kt<ktiles;kt++){
        float4 a0 = *(const float4*)(Ap);
        float4 a1 = *(const float4*)(Ap + (size_t)64*K);
        float4 b0 = *(const float4*)(Bp);
        float4 b1 = *(const float4*)(Bp + (size_t)64*K);
        __syncthreads();
        As[lc+0][lr]=a0.x; As[lc+1][lr]=a0.y; As[lc+2][lr]=a0.z; As[lc+3][lr]=a0.w;
        As[lc+0][lr+64]=a1.x; As[lc+1][lr+64]=a1.y; As[lc+2][lr+64]=a1.z; As[lc+3][lr+64]=a1.w;
        Bs[lc+0][lr]=b0.x; Bs[lc+1][lr]=b0.y; Bs[lc+2][lr]=b0.z; Bs[lc+3][lr]=b0.w;
        Bs[lc+0][lr+64]=b1.x; Bs[lc+1][lr+64]=b1.y; Bs[lc+2][lr+64]=b1.z; Bs[lc+3][lr+64]=b1.w;
        __syncthreads();
#pragma unroll
        for(int k=0;k<16;k++){
            float4 x0 = *(float4*)&As[k][ty<<3];
            float4 x1 = *(float4*)&As[k][(ty<<3)+4];
            float4 y0 = *(float4*)&Bs[k][tx<<3];
            float4 y1 = *(float4*)&Bs[k][(tx<<3)+4];
            float av[8] = {x0.x,x0.y,x0.z,x0.w,x1.x,x1.y,x1.z,x1.w};
            float bv[8] = {y0.x,y0.y,y0.z,y0.w,y1.x,y1.y,y1.z,y1.w};
#pragma unroll
            for(int i=0;i<8;i++)
#pragma unroll
                for(int j=0;j<8;j++) acc[i][j] += av[i]*bv[j];
        }
        Ap += 16; Bp += 16;
    }
#pragma unroll
    for(int i=0;i<8;i++){
        int m = bm + (ty<<3) + i;
        int n0 = bn + (tx<<3);
        float* cr = C + (size_t)m*Nn + n0;
        float* zr = (mode==2) ? Z + (size_t)m*Nn + n0 : nullptr;
#pragma unroll
        for(int j=0;j<8;j++){
            float v = acc[i][j] + bias[n0+j];
            if(mode==1) v = 1.f/(1.f+expf(-v));
            cr[j] = v;
            if(mode==2) zr[j] -= v;
        }
    }
}

// ------------------------------------------------------------------ mhesa recurrence (in place)
__global__ void mhesa_rec_k(float* __restrict__ h1, const float* __restrict__ alpha_raw,
                            const float* __restrict__ init, int layer){
    int id = blockIdx.x*256 + threadIdx.x;   // 8192
    int b = id >> 9, d = id & 511;
    float al = sigm(alpha_raw[layer*HH + (d>>6)]);
    float om = 1.f - al;
    float ini = init[layer*DD + d];
    float* p = h1 + (size_t)b*NN*DD + d;
    float prev = ini, S = 0.f, pw = om;
    for(int t=0;t<NN;t+=8){
        float v[8];
#pragma unroll
        for(int j=0;j<8;j++) v[j] = p[(size_t)(t+j)*DD];
#pragma unroll
        for(int j=0;j<8;j++){
            float u = v[j] - prev; prev = v[j];
            S = om*S + al*u;
            v[j] = S + pw*ini;
            pw *= om;
        }
#pragma unroll
        for(int j=0;j<8;j++) p[(size_t)(t+j)*DD] = v[j];
    }
}

// ------------------------------------------------------------------ 7-wide projection  out = A@W^T + b
__global__ void proj7_k(const float* __restrict__ A, const float* __restrict__ W,
                        const float* __restrict__ bias, float* __restrict__ out){
    int gw = (blockIdx.x*256 + threadIdx.x) >> 5;   // row
    int lane = threadIdx.x & 31;
    if(gw >= BB*NN) return;
    const float* ra = A + (size_t)gw*DD;
    float acc[TFc];
#pragma unroll
    for(int f=0;f<TFc;f++) acc[f] = 0.f;
    for(int k=lane;k<DD;k+=32){
        float a = ra[k];
#pragma unroll
        for(int f=0;f<TFc;f++) acc[f] += a*W[f*DD+k];
    }
#pragma unroll
    for(int f=0;f<TFc;f++)
#pragma unroll
        for(int o=16;o>0;o>>=1) acc[f] += __shfl_xor_sync(0xffffffffu, acc[f], o);
    if(lane==0){
#pragma unroll
        for(int f=0;f<TFc;f++) out[(size_t)gw*TFc + f] = acc[f] + bias[f];
    }
}

// ------------------------------------------------------------------ level recurrences (in place on xl)
__global__ void level_rec_k(float* __restrict__ xl, const float* __restrict__ sp,
                            const float* __restrict__ gp,
                            const float* __restrict__ lv_alpha, int layer){
    int id = threadIdx.x;
    if(id >= BB*TFc) return;
    int b = id / TFc, f = id % TFc;
    float al = sigm(lv_alpha[layer]);
    float om = 1.f - al;
    float t1 = 0.f, t2 = 0.f;
    size_t base = (size_t)b*NN*TFc + f;
    for(int t=0;t<NN;t+=4){
        float xv[4], sv[4], gv[4];
#pragma unroll
        for(int j=0;j<4;j++){
            size_t ix = base + (size_t)(t+j)*TFc;
            xv[j]=xl[ix]; sv[j]=sp[ix]; gv[j]=gp[ix];
        }
#pragma unroll
        for(int j=0;j<4;j++){
            t1 = om*t1 + al*(xv[j]-sv[j]);
            t2 = om*t2 + gv[j];
            xv[j] = t1 + t2;
        }
#pragma unroll
        for(int j=0;j<4;j++) xl[base + (size_t)(t+j)*TFc] = xv[j];
    }
}

// ------------------------------------------------------------------ layer norm  out = LN(a [+ b2])*g + bb
__global__ void ln_k(const float* __restrict__ a, const float* __restrict__ b2,
                     const float* __restrict__ g, const float* __restrict__ bb,
                     float* __restrict__ out){
    __shared__ float v[DD];
    __shared__ float red[256];
    int row = blockIdx.x, tid = threadIdx.x;
    const float* ra = a + (size_t)row*DD;
    const float* rb = b2 ? b2 + (size_t)row*DD : nullptr;
    float s = 0.f;
    for(int i=tid;i<DD;i+=256){
        float x = ra[i] + (rb ? rb[i] : 0.f);
        v[i] = x; s += x;
    }
    red[tid] = s; __syncthreads();
    for(int st=128;st>0;st>>=1){ if(tid<st) red[tid]+=red[tid+st]; __syncthreads(); }
    float mu = red[0] * (1.f/DD);
    __syncthreads();
    s = 0.f;
    for(int i=tid;i<DD;i+=256){ float dd = v[i]-mu; s += dd*dd; }
    red[tid] = s; __syncthreads();
    for(int st=128;st>0;st>>=1){ if(tid<st) red[tid]+=red[tid+st]; __syncthreads(); }
    float inv = 1.f/sqrtf(red[0]*(1.f/DD) + 1e-5f);
    for(int i=tid;i<DD;i+=256)
        out[(size_t)row*DD + i] = (v[i]-mu)*inv*g[i] + bb[i];
}

// ------------------------------------------------------------------ dampening prefix sums
__global__ void pw_k(const float* __restrict__ dampen, float* __restrict__ pw){
    int h = threadIdx.x;
    if(h >= HH) return;
    float df = sigm(dampen[h]);
    float c = 0.f;
    for(int t=0;t<TT;t++){ c += powf(df, (float)(t+1)); pw[t*HH+h] = c; }
}

// ------------------------------------------------------------------ extra + damp  ->  S[b,t,d]
__global__ void extra_damp_k(const float* __restrict__ lastg, const float* __restrict__ pw,
                             const int* __restrict__ NK, const int* __restrict__ KF,
                             const float2* __restrict__ KV, float* __restrict__ S){
    int d = threadIdx.x;
    int t = blockIdx.x, b = blockIdx.y;
    float pwv = pw[t*HH + (d>>6)];
    float tt = (float)(NN + t);
    float acc = 0.f;
#pragma unroll
    for(int l=0;l<2;l++){
        int seq = l*BB*DD + b*DD + d;
        acc += lastg[seq] * pwv;
        int nk = NK[seq];
        float e = 0.f;
        for(int q=0;q<nk;q++){
            int f = KF[seq*16+q];
            float2 X = KV[seq*16+q];
            float sa, ca;
            float ang = ((6.2831855f*(float)f)*tt)*(1.f/2048.f);   // replicate fp32 chain
            sincosf(ang, &sa, &ca);
            e += X.x*ca - X.y*sa;
            if(f != 0 && f != 1024){
                float ang2 = ((6.2831855f*(float)(2048-f))*tt)*(1.f/2048.f);
                sincosf(ang2, &sa, &ca);
                e += X.x*ca + X.y*sa;    // conjugate bin
            }
        }
        acc += e*(1.f/2048.f);
    }
    S[((size_t)b*TT + t)*DD + d] = acc;
}

// ------------------------------------------------------------------ final  out[b,t,f]
__global__ void final_k(const float* __restrict__ S, const float* __restrict__ xl,
                        const float* __restrict__ ltf_w, const float* __restrict__ ltf_b,
                        float* __restrict__ out){
    int id = blockIdx.x*256 + threadIdx.x;
    if(id >= BB*TT*TFc) return;
    int f = id % TFc;
    int t = (id/TFc) % TT;
    int b = id/(TFc*TT);
    const float* sr = S + ((size_t)b*TT + t)*DD;
    const float* wr = ltf_w + (size_t)f*DD;
    float acc = 0.f;
    for(int k=0;k<DD;k++) acc += sr[k]*wr[k];
    out[id] = xl[((size_t)b*NN + (NN-1))*TFc + f] + acc + ltf_b[f];
}

// ------------------------------------------------------------------ launcher
extern "C" void kernel_launch(void* const* d_in, const int* in_sizes, int n_in,
                              void* d_out, int out_size){
    // Hedge on num_steps_forecast position: dict order puts the int32 scalar
    // (size 1) at index 1; signature order puts it last. embed_w has 10752
    // elements, so in_sizes[1]==1 discriminates.
    int base = (n_in >= 2 && in_sizes[1] == 1) ? 2 : 1;

    const float* x        = (const float*)d_in[0];
    const float* embed_w  = (const float*)d_in[base+0];
    const float* embed_b  = (const float*)d_in[base+1];
    const float* mh_init  = (const float*)d_in[base+2];
    const float* mh_alpha = (const float*)d_in[base+3];
    const float* pin_w    = (const float*)d_in[base+4];
    const float* pin_b    = (const float*)d_in[base+5];
    const float* pout_w   = (const float*)d_in[base+6];
    const float* pout_b   = (const float*)d_in[base+7];
    const float* n1g      = (const float*)d_in[base+8];
    const float* n1b      = (const float*)d_in[base+9];
    const float* ff1w     = (const float*)d_in[base+10];
    const float* ff1b     = (const float*)d_in[base+11];
    const float* ff2w     = (const float*)d_in[base+12];
    const float* ff2b     = (const float*)d_in[base+13];
    const float* n2g      = (const float*)d_in[base+14];
    const float* n2b      = (const float*)d_in[base+15];
    const float* lv_alpha = (const float*)d_in[base+16];
    const float* tg_w     = (const float*)d_in[base+17];
    const float* tg_b     = (const float*)d_in[base+18];
    const float* ts_w     = (const float*)d_in[base+19];
    const float* ts_b     = (const float*)d_in[base+20];
    const float* dampen   = (const float*)d_in[base+21];
    const float* ltf_w    = (const float*)d_in[base+22];
    const float* ltf_b    = (const float*)d_in[base+23];
    float* out = (float*)d_out;

    float* G = nullptr;
    cudaGetSymbolAddress((void**)&G, g_buf);

    float* Zb  = G;
    float* H1  = G + 1*BND;
    float* LS  = G + 2*BND;
    float* LG  = G + 3*BND;
    float* ZN  = G + 4*BND;
    float* FFO = G + 5*BND;
    float* HID = G + 6*BND;     // 4*BND
    size_t o = 10*BND;
    float* SP    = G + o; o += 229376;
    float* GP    = G + o; o += 229376;
    float* XL    = G + o; o += 229376;
    float* Sb    = G + o; o += 786432;
    float* LASTG = G + o; o += 16384;
    float* PW    = G + o; o += 768;
    int*   NKp   = (int*)(G + o); o += 16384;
    int*   KFp   = (int*)(G + o); o += 262144;
    float2* KVp  = (float2*)(G + o);

    copy_k<<<896,256>>>(x, XL, BB*NN*TFc);
    embed_k<<<dim3(4,NN,BB),128>>>(x, embed_w, embed_b, Zb);

    for(int l=0;l<2;l++){
        freqatt_k<<<dim3(DD,BB),256>>>(Zb, LS, NKp + l*8192, KFp + l*8192*16,
                                       KVp + (size_t)l*8192*16);
        gemm_k<<<dim3(4,256),256>>>(Zb, pin_w + (size_t)l*DD*DD, pin_b + l*DD,
                                    H1, nullptr, BB*NN, DD, DD, 0);
        mhesa_rec_k<<<32,256>>>(H1, mh_alpha, mh_init, l);
        gemm_k<<<dim3(4,256),256>>>(H1, pout_w + (size_t)l*DD*DD, pout_b + l*DD,
                                    LG, Zb, BB*NN, DD, DD, 2);
        copy_lastg_k<<<32,256>>>(LG, LASTG + l*8192);
        proj7_k<<<4096,256>>>(LS, ts_w + l*TFc*DD, ts_b + l*TFc, SP);
        proj7_k<<<4096,256>>>(LG, tg_w + l*TFc*DD, tg_b + l*TFc, GP);
        level_rec_k<<<1,128>>>(XL, SP, GP, lv_alpha, l);
        if(l == 0){
            ln_k<<<BB*NN,256>>>(Zb, nullptr, n1g, n1b, ZN);
            gemm_k<<<dim3(16,256),256>>>(ZN, ff1w, ff1b, HID, nullptr, BB*NN, 4*DD, DD, 1);
            gemm_k<<<dim3(4,256),256>>>(HID, ff2w, ff2b, FFO, nullptr, BB*NN, DD, 4*DD, 0);
            ln_k<<<BB*NN,256>>>(ZN, FFO, n2g, n2b, Zb);
        }
    }

    pw_k<<<1,8>>>(dampen, PW);
    extra_damp_k<<<dim3(TT,BB),512>>>(LASTG, PW, NKp, KFp, KVp, Sb);
    final_k<<<42,256>>>(Sb, XL, ltf_w, ltf_b, out);
}

// round 8
// speedup vs baseline: 1.2935x; 1.2935x over previous
#include <cuda_runtime.h>
#include <math.h>
#include <stdint.h>

#define BB 16
#define NN 2048
#define DD 512
#define TFc 7
#define HH 8
#define TT 96
#define BND 16777216ull   // 16*2048*512

typedef unsigned long long u64;

// scratch: 10*BND + small tail
__device__ float g_buf[170066688];

__device__ __forceinline__ float sigm(float x){ return 1.f/(1.f+expf(-x)); }

__device__ __forceinline__ u64 pk2(float lo, float hi){
    u64 r; asm("mov.b64 %0, {%1,%2};" : "=l"(r) : "f"(lo), "f"(hi)); return r;
}
__device__ __forceinline__ void fma2(u64& d, u64 a, u64 b){
    asm("fma.rn.f32x2 %0, %1, %2, %0;" : "+l"(d) : "l"(a), "l"(b));
}
__device__ __forceinline__ float2 upk2(u64 v){
    float2 f; asm("mov.b64 {%0,%1}, %2;" : "=f"(f.x), "=f"(f.y) : "l"(v)); return f;
}

// ------------------------------------------------------------------ utils
__global__ void copy_k(const float* __restrict__ a, float* __restrict__ b, int n){
    int i = blockIdx.x*256 + threadIdx.x;
    if(i < n) b[i] = a[i];
}

__global__ void copy_lastg_k(const float* __restrict__ lg, float* __restrict__ dst){
    int id = blockIdx.x*256 + threadIdx.x;   // 8192
    int b = id >> 9, d = id & 511;
    dst[id] = lg[(size_t)b*NN*DD + (size_t)(NN-1)*DD + d];
}

// ------------------------------------------------------------------ transpose [b,R,C] -> [b,C,R]
__global__ void transpose_k(const float* __restrict__ src, float* __restrict__ dst,
                            int R, int C){
    __shared__ float t[32][33];
    int b = blockIdx.z;
    int c0 = blockIdx.x << 5, r0 = blockIdx.y << 5;
    const float* s = src + (size_t)b*R*C;
    float* d = dst + (size_t)b*R*C;
#pragma unroll
    for(int i=threadIdx.y;i<32;i+=8)
        t[i][threadIdx.x] = s[(size_t)(r0+i)*C + c0 + threadIdx.x];
    __syncthreads();
#pragma unroll
    for(int i=threadIdx.y;i<32;i+=8)
        d[(size_t)(c0+i)*R + r0 + threadIdx.x] = t[threadIdx.x][i];
}

// ------------------------------------------------------------------ embed
__global__ void embed_k(const float* __restrict__ x, const float* __restrict__ w,
                        const float* __restrict__ eb, float* __restrict__ z){
    int d = blockIdx.x*128 + threadIdx.x;
    int n = blockIdx.y, b = blockIdx.z;
    float acc = eb[d];
#pragma unroll
    for(int k=0;k<3;k++){
        int nn = n + k - 1;
        if(nn < 0 || nn >= NN) continue;
        const float* xr = x + ((size_t)b*NN + nn)*TFc;
        const float* wr = w + (size_t)d*21 + k;
#pragma unroll
        for(int c=0;c<TFc;c++) acc += xr[c]*wr[c*3];
    }
    z[((size_t)b*NN + n)*DD + d] = acc;
}

// ------------------------------------------------------------------ freq attention (transposed layout)
// zt, lst: [b, d, n] contiguous rows. DIF FFT (natural in, bit-reversed out).
__global__ void freqatt_k(float* __restrict__ zt, float* __restrict__ lst,
                          int* __restrict__ NKo, int* __restrict__ KFo,
                          float2* __restrict__ KVo){
    __shared__ float2 X[2048];
    __shared__ float2 tw[1024];
    __shared__ float amp2[1025];
    __shared__ float rv[256];
    __shared__ int   ri[256];
    __shared__ int   kept[32];
    __shared__ int   nkept;
    __shared__ float thr_s;

    int d = blockIdx.x, b = blockIdx.y, tid = threadIdx.x;
    float* row = zt + ((size_t)b*DD + d)*NN;

    for(int j=tid;j<1024;j+=256){
        float sa,ca;
        sincosf(-3.14159265358979323846f*(float)j*(1.f/1024.f), &sa, &ca);
        tw[j] = make_float2(ca, sa);
    }
    for(int j=tid;j<2048;j+=256)
        X[j] = make_float2(row[j], 0.f);     // coalesced, natural order
    if(tid==0) nkept = 0;
    __syncthreads();

    // 11 radix-2 DIF stages (stride 1024 -> 1); output bit-reversed
    for(int s=11;s>=1;s--){
        int half = 1 << (s-1);
        int tsh  = 11 - s;
        for(int k=tid;k<1024;k+=256){
            int j  = k & (half-1);
            int i1 = ((k >> (s-1)) << s) | j;
            int i2 = i1 + half;
            float2 w = tw[j << tsh];
            float2 u = X[i1], v = X[i2];
            float dr = u.x - v.x, di = u.y - v.y;
            X[i1] = make_float2(u.x+v.x, u.y+v.y);
            X[i2] = make_float2(dr*w.x - di*w.y, dr*w.y + di*w.x);
        }
        __syncthreads();
    }
    // spectrum bin f lives at X[brev11(f)]
    for(int f=tid;f<=1024;f+=256){
        int rf = (int)(__brev((unsigned)f) >> 21);
        float2 v = X[rf];
        amp2[f] = v.x*v.x + v.y*v.y;
    }
    __syncthreads();

    // 4 argmax rounds -> threshold = 4th largest amp^2
    for(int r=0;r<4;r++){
        float bv = -1.f; int bi = 0;
        for(int f=tid;f<=1024;f+=256){
            float v = amp2[f];
            if(v > bv){ bv = v; bi = f; }
        }
        rv[tid] = bv; ri[tid] = bi;
        __syncthreads();
        for(int st=128;st>0;st>>=1){
            if(tid < st && rv[tid+st] > rv[tid]){ rv[tid]=rv[tid+st]; ri[tid]=ri[tid+st]; }
            __syncthreads();
        }
        if(tid==0){
            if(r < 3){ kept[nkept] = ri[0]; nkept++; amp2[ri[0]] = -2.f; }
            else thr_s = rv[0];
        }
        __syncthreads();
    }
    float thr = thr_s;
    for(int f=tid;f<=1024;f+=256){
        if(amp2[f] >= thr){
            int p = atomicAdd(&nkept, 1);
            if(p < 32) kept[p] = f;
        }
    }
    __syncthreads();
    int nk = min(nkept, 32);
    if(tid == 0){  // deterministic order
        for(int i=1;i<nk;i++){
            int key = kept[i], j = i-1;
            while(j >= 0 && kept[j] > key){ kept[j+1] = kept[j]; j--; }
            kept[j+1] = key;
        }
    }
    __syncthreads();

    // sparse inverse rFFT; write lst row, zt row -= (coalesced)
    float* lrow = lst + ((size_t)b*DD + d)*NN;
    for(int n=tid;n<2048;n+=256){
        float acc = 0.f;
        for(int q=0;q<nk;q++){
            int f = kept[q];
            int rf = (int)(__brev((unsigned)f) >> 21);
            float2 Xf = X[rf];
            float wq = (f==0 || f==1024) ? 1.f : 2.f;
            int ph = (f*n) & 2047;
            float2 t = tw[ph & 1023];
            float sg = (ph & 1024) ? -1.f : 1.f;
            float ca = sg*t.x, sa = -sg*t.y;      // e^{+i*2*pi*ph/2048}
            acc += wq*(Xf.x*ca - Xf.y*sa);
        }
        acc *= (1.f/2048.f);
        lrow[n] = acc;
        row[n] -= acc;
    }

    int ns = min(nk, 16);
    int seq = b*DD + d;
    if(tid==0) NKo[seq] = ns;
    if(tid < ns){
        int f = kept[tid];
        KFo[seq*16 + tid] = f;
        KVo[seq*16 + tid] = X[(int)(__brev((unsigned)f) >> 21)];
    }
}

// ------------------------------------------------------------------ GEMM  C = A@W^T + bias
// double-buffered smem + packed fma.rn.f32x2.
// mode 0: store; 1: sigmoid store; 2: store and Z -= C.
__global__ __launch_bounds__(256,2)
void gemm_k(const float* __restrict__ A, const float* __restrict__ W,
            const float* __restrict__ bias, float* __restrict__ C,
            float* __restrict__ Z, int M, int Nn, int K, int mode){
    __shared__ float As[2][16][132];
    __shared__ float Bs[2][16][132];
    int bm = blockIdx.y << 7, bn = blockIdx.x << 7;
    int tid = threadIdx.x;
    int tx = tid & 15, ty = tid >> 4;
    int lr = tid >> 2;            // 0..63
    int lc = (tid & 3) << 2;      // 0,4,8,12
    u64 acc2[8][4];
#pragma unroll
    for(int i=0;i<8;i++)
#pragma unroll
        for(int j=0;j<4;j++) acc2[i][j] = 0ull;

    const float* Ap = A + (size_t)(bm+lr)*K + lc;
    const float* Bp = W + (size_t)(bn+lr)*K + lc;
    int ktiles = K >> 4;

    float4 a0 = *(const float4*)(Ap);
    float4 a1 = *(const float4*)(Ap + (size_t)64*K);
    float4 b0 = *(const float4*)(Bp);
    float4 b1 = *(const float4*)(Bp + (size_t)64*K);
    As[0][lc+0][lr]=a0.x; As[0][lc+1][lr]=a0.y; As[0][lc+2][lr]=a0.z; As[0][lc+3][lr]=a0.w;
    As[0][lc+0][lr+64]=a1.x; As[0][lc+1][lr+64]=a1.y; As[0][lc+2][lr+64]=a1.z; As[0][lc+3][lr+64]=a1.w;
    Bs[0][lc+0][lr]=b0.x; Bs[0][lc+1][lr]=b0.y; Bs[0][lc+2][lr]=b0.z; Bs[0][lc+3][lr]=b0.w;
    Bs[0][lc+0][lr+64]=b1.x; Bs[0][lc+1][lr+64]=b1.y; Bs[0][lc+2][lr+64]=b1.z; Bs[0][lc+3][lr+64]=b1.w;
    __syncthreads();

    int p = 0;
    for(int kt=0;kt<ktiles;kt++){
        if(kt+1 < ktiles){
            Ap += 16; Bp += 16;
            a0 = *(const float4*)(Ap);
            a1 = *(const float4*)(Ap + (size_t)64*K);
            b0 = *(const float4*)(Bp);
            b1 = *(const float4*)(Bp + (size_t)64*K);
        }
#pragma unroll
        for(int k=0;k<16;k++){
            float4 x0 = *(float4*)&As[p][k][ty<<3];
            float4 x1 = *(float4*)&As[p][k][(ty<<3)+4];
            float4 y0 = *(float4*)&Bs[p][k][tx<<3];
            float4 y1 = *(float4*)&Bs[p][k][(tx<<3)+4];
            u64 bw[4] = { pk2(y0.x,y0.y), pk2(y0.z,y0.w), pk2(y1.x,y1.y), pk2(y1.z,y1.w) };
            float av[8] = {x0.x,x0.y,x0.z,x0.w,x1.x,x1.y,x1.z,x1.w};
#pragma unroll
            for(int i=0;i<8;i++){
                u64 aw = pk2(av[i], av[i]);
#pragma unroll
                for(int j=0;j<4;j++) fma2(acc2[i][j], aw, bw[j]);
            }
        }
        if(kt+1 < ktiles){
            __syncthreads();
            int q = p ^ 1;
            As[q][lc+0][lr]=a0.x; As[q][lc+1][lr]=a0.y; As[q][lc+2][lr]=a0.z; As[q][lc+3][lr]=a0.w;
            As[q][lc+0][lr+64]=a1.x; As[q][lc+1][lr+64]=a1.y; As[q][lc+2][lr+64]=a1.z; As[q][lc+3][lr+64]=a1.w;
            Bs[q][lc+0][lr]=b0.x; Bs[q][lc+1][lr]=b0.y; Bs[q][lc+2][lr]=b0.z; Bs[q][lc+3][lr]=b0.w;
            Bs[q][lc+0][lr+64]=b1.x; Bs[q][lc+1][lr+64]=b1.y; Bs[q][lc+2][lr+64]=b1.z; Bs[q][lc+3][lr+64]=b1.w;
            __syncthreads();
            p = q;
        }
    }

#pragma unroll
    for(int i=0;i<8;i++){
        int m = bm + (ty<<3) + i;
        int n0 = bn + (tx<<3);
        float* cr = C + (size_t)m*Nn + n0;
        float* zr = (mode==2) ? Z + (size_t)m*Nn + n0 : nullptr;
#pragma unroll
        for(int j=0;j<4;j++){
            float2 v = upk2(acc2[i][j]);
            float v0 = v.x + bias[n0+2*j];
            float v1 = v.y + bias[n0+2*j+1];
            if(mode==1){ v0 = 1.f/(1.f+expf(-v0)); v1 = 1.f/(1.f+expf(-v1)); }
            cr[2*j] = v0; cr[2*j+1] = v1;
            if(mode==2){ zr[2*j] -= v0; zr[2*j+1] -= v1; }
        }
    }
}

// ------------------------------------------------------------------ mhesa recurrence (in place)
__global__ void mhesa_rec_k(float* __restrict__ h1, const float* __restrict__ alpha_raw,
                            const float* __restrict__ init, int layer){
    int id = blockIdx.x*256 + threadIdx.x;   // 8192
    int b = id >> 9, d = id & 511;
    float al = sigm(alpha_raw[layer*HH + (d>>6)]);
    float om = 1.f - al;
    float ini = init[layer*DD + d];
    float* p = h1 + (size_t)b*NN*DD + d;
    float prev = ini, S = 0.f, pw = om;
    for(int t=0;t<NN;t+=8){
        float v[8];
#pragma unroll
        for(int j=0;j<8;j++) v[j] = p[(size_t)(t+j)*DD];
#pragma unroll
        for(int j=0;j<8;j++){
            float u = v[j] - prev; prev = v[j];
            S = om*S + al*u;
            v[j] = S + pw*ini;
            pw *= om;
        }
#pragma unroll
        for(int j=0;j<8;j++) p[(size_t)(t+j)*DD] = v[j];
    }
}

// ------------------------------------------------------------------ projection from transposed latents
// SP[b,n,f] = sum_d LST[b,d,n]*W[f,d] + bias[f]
__global__ void projT_k(const float* __restrict__ LST, const float* __restrict__ W,
                        const float* __restrict__ bias, float* __restrict__ SP){
    __shared__ float w[TFc][DD];
    int b = blockIdx.y, tid = threadIdx.x;
    int n = (blockIdx.x << 8) + tid;
    for(int i=tid;i<TFc*DD;i+=256) w[i/DD][i%DD] = W[i];
    __syncthreads();
    const float* base = LST + (size_t)b*DD*NN + n;
    float acc[TFc];
#pragma unroll
    for(int f=0;f<TFc;f++) acc[f] = 0.f;
    for(int d=0;d<DD;d++){
        float v = base[(size_t)d*NN];
#pragma unroll
        for(int f=0;f<TFc;f++) acc[f] += w[f][d]*v;
    }
    float* o = SP + ((size_t)b*NN + n)*TFc;
#pragma unroll
    for(int f=0;f<TFc;f++) o[f] = acc[f] + bias[f];
}

// ------------------------------------------------------------------ 7-wide projection (row layout)
__global__ void proj7_k(const float* __restrict__ A, const float* __restrict__ W,
                        const float* __restrict__ bias, float* __restrict__ out){
    int gw = (blockIdx.x*256 + threadIdx.x) >> 5;   // row
    int lane = threadIdx.x & 31;
    if(gw >= BB*NN) return;
    const float* ra = A + (size_t)gw*DD;
    float acc[TFc];
#pragma unroll
    for(int f=0;f<TFc;f++) acc[f] = 0.f;
    for(int k=lane;k<DD;k+=32){
        float a = ra[k];
#pragma unroll
        for(int f=0;f<TFc;f++) acc[f] += a*W[f*DD+k];
    }
#pragma unroll
    for(int f=0;f<TFc;f++)
#pragma unroll
        for(int o=16;o>0;o>>=1) acc[f] += __shfl_xor_sync(0xffffffffu, acc[f], o);
    if(lane==0){
#pragma unroll
        for(int f=0;f<TFc;f++) out[(size_t)gw*TFc + f] = acc[f] + bias[f];
    }
}

// ------------------------------------------------------------------ level recurrences (in place on xl)
__global__ void level_rec_k(float* __restrict__ xl, const float* __restrict__ sp,
                            const float* __restrict__ gp,
                            const float* __restrict__ lv_alpha, int layer){
    int id = threadIdx.x;
    if(id >= BB*TFc) return;
    int b = id / TFc, f = id % TFc;
    float al = sigm(lv_alpha[layer]);
    float om = 1.f - al;
    float t1 = 0.f, t2 = 0.f;
    size_t base = (size_t)b*NN*TFc + f;
    for(int t=0;t<NN;t+=4){
        float xv[4], sv[4], gv[4];
#pragma unroll
        for(int j=0;j<4;j++){
            size_t ix = base + (size_t)(t+j)*TFc;
            xv[j]=xl[ix]; sv[j]=sp[ix]; gv[j]=gp[ix];
        }
#pragma unroll
        for(int j=0;j<4;j++){
            t1 = om*t1 + al*(xv[j]-sv[j]);
            t2 = om*t2 + gv[j];
            xv[j] = t1 + t2;
        }
#pragma unroll
        for(int j=0;j<4;j++) xl[base + (size_t)(t+j)*TFc] = xv[j];
    }
}

// ------------------------------------------------------------------ layer norm
__global__ void ln_k(const float* __restrict__ a, const float* __restrict__ b2,
                     const float* __restrict__ g, const float* __restrict__ bb,
                     float* __restrict__ out){
    __shared__ float v[DD];
    __shared__ float red[256];
    int row = blockIdx.x, tid = threadIdx.x;
    const float* ra = a + (size_t)row*DD;
    const float* rb = b2 ? b2 + (size_t)row*DD : nullptr;
    float s = 0.f;
    for(int i=tid;i<DD;i+=256){
        float x = ra[i] + (rb ? rb[i] : 0.f);
        v[i] = x; s += x;
    }
    red[tid] = s; __syncthreads();
    for(int st=128;st>0;st>>=1){ if(tid<st) red[tid]+=red[tid+st]; __syncthreads(); }
    float mu = red[0] * (1.f/DD);
    __syncthreads();
    s = 0.f;
    for(int i=tid;i<DD;i+=256){ float dd = v[i]-mu; s += dd*dd; }
    red[tid] = s; __syncthreads();
    for(int st=128;st>0;st>>=1){ if(tid<st) red[tid]+=red[tid+st]; __syncthreads(); }
    float inv = 1.f/sqrtf(red[0]*(1.f/DD) + 1e-5f);
    for(int i=tid;i<DD;i+=256)
        out[(size_t)row*DD + i] = (v[i]-mu)*inv*g[i] + bb[i];
}

// ------------------------------------------------------------------ dampening prefix sums
__global__ void pw_k(const float* __restrict__ dampen, float* __restrict__ pw){
    int h = threadIdx.x;
    if(h >= HH) return;
    float df = sigm(dampen[h]);
    float c = 0.f;
    for(int t=0;t<TT;t++){ c += powf(df, (float)(t+1)); pw[t*HH+h] = c; }
}

// ------------------------------------------------------------------ extra + damp  ->  S[b,t,d]
__global__ void extra_damp_k(const float* __restrict__ lastg, const float* __restrict__ pw,
                             const int* __restrict__ NK, const int* __restrict__ KF,
                             const float2* __restrict__ KV, float* __restrict__ S){
    int d = threadIdx.x;
    int t = blockIdx.x, b = blockIdx.y;
    float pwv = pw[t*HH + (d>>6)];
    float tt = (float)(NN + t);
    float acc = 0.f;
#pragma unroll
    for(int l=0;l<2;l++){
        int seq = l*BB*DD + b*DD + d;
        acc += lastg[seq] * pwv;
        int nk = NK[seq];
        float e = 0.f;
        for(int q=0;q<nk;q++){
            int f = KF[seq*16+q];
            float2 X = KV[seq*16+q];
            float sa, ca;
            float ang = ((6.2831855f*(float)f)*tt)*(1.f/2048.f);   // replicate fp32 chain
            sincosf(ang, &sa, &ca);
            e += X.x*ca - X.y*sa;
            if(f != 0 && f != 1024){
                float ang2 = ((6.2831855f*(float)(2048-f))*tt)*(1.f/2048.f);
                sincosf(ang2, &sa, &ca);
                e += X.x*ca + X.y*sa;    // conjugate bin
            }
        }
        acc += e*(1.f/2048.f);
    }
    S[((size_t)b*TT + t)*DD + d] = acc;
}

// ------------------------------------------------------------------ final  out[b,t,f]
__global__ void final_k(const float* __restrict__ S, const float* __restrict__ xl,
                        const float* __restrict__ ltf_w, const float* __restrict__ ltf_b,
                        float* __restrict__ out){
    int id = blockIdx.x*256 + threadIdx.x;
    if(id >= BB*TT*TFc) return;
    int f = id % TFc;
    int t = (id/TFc) % TT;
    int b = id/(TFc*TT);
    const float* sr = S + ((size_t)b*TT + t)*DD;
    const float* wr = ltf_w + (size_t)f*DD;
    float acc = 0.f;
    for(int k=0;k<DD;k++) acc += sr[k]*wr[k];
    out[id] = xl[((size_t)b*NN + (NN-1))*TFc + f] + acc + ltf_b[f];
}

// ------------------------------------------------------------------ launcher
extern "C" void kernel_launch(void* const* d_in, const int* in_sizes, int n_in,
                              void* d_out, int out_size){
    int base = (n_in >= 2 && in_sizes[1] == 1) ? 2 : 1;

    const float* x        = (const float*)d_in[0];
    const float* embed_w  = (const float*)d_in[base+0];
    const float* embed_b  = (const float*)d_in[base+1];
    const float* mh_init  = (const float*)d_in[base+2];
    const float* mh_alpha = (const float*)d_in[base+3];
    const float* pin_w    = (const float*)d_in[base+4];
    const float* pin_b    = (const float*)d_in[base+5];
    const float* pout_w   = (const float*)d_in[base+6];
    const float* pout_b   = (const float*)d_in[base+7];
    const float* n1g      = (const float*)d_in[base+8];
    const float* n1b      = (const float*)d_in[base+9];
    const float* ff1w     = (const float*)d_in[base+10];
    const float* ff1b     = (const float*)d_in[base+11];
    const float* ff2w     = (const float*)d_in[base+12];
    const float* ff2b     = (const float*)d_in[base+13];
    const float* n2g      = (const float*)d_in[base+14];
    const float* n2b      = (const float*)d_in[base+15];
    const float* lv_alpha = (const float*)d_in[base+16];
    const float* tg_w     = (const float*)d_in[base+17];
    const float* tg_b     = (const float*)d_in[base+18];
    const float* ts_w     = (const float*)d_in[base+19];
    const float* ts_b     = (const float*)d_in[base+20];
    const float* dampen   = (const float*)d_in[base+21];
    const float* ltf_w    = (const float*)d_in[base+22];
    const float* ltf_b    = (const float*)d_in[base+23];
    float* out = (float*)d_out;

    float* G = nullptr;
    cudaGetSymbolAddress((void**)&G, g_buf);

    float* Zb  = G;
    float* H1  = G + 1*BND;
    float* LG  = G + 3*BND;
    float* ZN  = G + 4*BND;
    float* FFO = G + 5*BND;
    float* ZT  = G + 6*BND;     // aliases HID (FF intermediate, 4*BND at 6*BND)
    float* LST = G + 7*BND;
    float* HID = G + 6*BND;
    size_t o = 10*BND;
    float* SP    = G + o; o += 229376;
    float* GP    = G + o; o += 229376;
    float* XL    = G + o; o += 229376;
    float* Sb    = G + o; o += 786432;
    float* LASTG = G + o; o += 16384;
    float* PW    = G + o; o += 768;
    int*   NKp   = (int*)(G + o); o += 16384;
    int*   KFp   = (int*)(G + o); o += 262144;
    float2* KVp  = (float2*)(G + o);

    copy_k<<<896,256>>>(x, XL, BB*NN*TFc);
    embed_k<<<dim3(4,NN,BB),128>>>(x, embed_w, embed_b, Zb);

    for(int l=0;l<2;l++){
        transpose_k<<<dim3(16,64,BB),dim3(32,8)>>>(Zb, ZT, NN, DD);
        freqatt_k<<<dim3(DD,BB),256>>>(ZT, LST, NKp + l*8192, KFp + l*8192*16,
                                       KVp + (size_t)l*8192*16);
        transpose_k<<<dim3(64,16,BB),dim3(32,8)>>>(ZT, Zb, DD, NN);
        projT_k<<<dim3(8,BB),256>>>(LST, ts_w + l*TFc*DD, ts_b + l*TFc, SP);
        gemm_k<<<dim3(4,256),256>>>(Zb, pin_w + (size_t)l*DD*DD, pin_b + l*DD,
                                    H1, nullptr, BB*NN, DD, DD, 0);
        mhesa_rec_k<<<32,256>>>(H1, mh_alpha, mh_init, l);
        gemm_k<<<dim3(4,256),256>>>(H1, pout_w + (size_t)l*DD*DD, pout_b + l*DD,
                                    LG, Zb, BB*NN, DD, DD, 2);
        copy_lastg_k<<<32,256>>>(LG, LASTG + l*8192);
        proj7_k<<<4096,256>>>(LG, tg_w + l*TFc*DD, tg_b + l*TFc, GP);
        level_rec_k<<<1,128>>>(XL, SP, GP, lv_alpha, l);
        if(l == 0){
            ln_k<<<BB*NN,256>>>(Zb, nullptr, n1g, n1b, ZN);
            gemm_k<<<dim3(16,256),256>>>(ZN, ff1w, ff1b, HID, nullptr, BB*NN, 4*DD, DD, 1);
            gemm_k<<<dim3(4,256),256>>>(HID, ff2w, ff2b, FFO, nullptr, BB*NN, DD, 4*DD, 0);
            ln_k<<<BB*NN,256>>>(ZN, FFO, n2g, n2b, Zb);
        }
    }

    pw_k<<<1,8>>>(dampen, PW);
    extra_damp_k<<<dim3(TT,BB),512>>>(LASTG, PW, NKp, KFp, KVp, Sb);
    final_k<<<42,256>>>(Sb, XL, ltf_w, ltf_b, out);
}

// round 15
// speedup vs baseline: 1.5783x; 1.2202x over previous
#include <cuda_runtime.h>
#include <math.h>
#include <stdint.h>

#define BB 16
#define NN 2048
#define DD 512
#define TFc 7
#define HH 8
#define TT 96
#define BND 16777216ull   // 16*2048*512

// scratch: 10*BND + small tail
__device__ float g_buf[170066688];

__device__ __forceinline__ float sigm(float x){ return 1.f/(1.f+expf(-x)); }

__device__ __forceinline__ uint32_t smem_u32(const void* p){
    uint32_t a;
    asm("{ .reg .u64 t; cvta.to.shared.u64 t, %1; cvt.u32.u64 %0, t; }" : "=r"(a) : "l"(p));
    return a;
}
__device__ __forceinline__ void split_tf(float v, uint32_t& hi, uint32_t& lo){
    asm("cvt.rna.tf32.f32 %0, %1;" : "=r"(hi) : "f"(v));
    float hf = __uint_as_float(hi);
    asm("cvt.rna.tf32.f32 %0, %1;" : "=r"(lo) : "f"(v - hf));
}
__device__ __forceinline__ void mma8(float* c, const uint32_t* a, const uint32_t* b){
    asm("mma.sync.aligned.m16n8k8.row.col.f32.tf32.tf32.f32 "
        "{%0,%1,%2,%3},{%4,%5,%6,%7},{%8,%9},{%0,%1,%2,%3};"
        : "+f"(c[0]), "+f"(c[1]), "+f"(c[2]), "+f"(c[3])
        : "r"(a[0]), "r"(a[1]), "r"(a[2]), "r"(a[3]), "r"(b[0]), "r"(b[1]));
}
#define CPA16(saddr, gptr) \
    asm volatile("cp.async.cg.shared.global [%0], [%1], 16;" :: "r"(saddr), "l"(gptr))

// ------------------------------------------------------------------ utils
__global__ void copy_k(const float* __restrict__ a, float* __restrict__ b, int n){
    int i = blockIdx.x*256 + threadIdx.x;
    if(i < n) b[i] = a[i];
}

__global__ void copy_lastg_k(const float* __restrict__ lg, float* __restrict__ dst){
    int id = blockIdx.x*256 + threadIdx.x;   // 8192
    int b = id >> 9, d = id & 511;
    dst[id] = lg[(size_t)b*NN*DD + (size_t)(NN-1)*DD + d];
}

// ------------------------------------------------------------------ transpose [b,R,C] -> [b,C,R]
__global__ void transpose_k(const float* __restrict__ src, float* __restrict__ dst,
                            int R, int C){
    __shared__ float t[32][33];
    int b = blockIdx.z;
    int c0 = blockIdx.x << 5, r0 = blockIdx.y << 5;
    const float* s = src + (size_t)b*R*C;
    float* d = dst + (size_t)b*R*C;
#pragma unroll
    for(int i=threadIdx.y;i<32;i+=8)
        t[i][threadIdx.x] = s[(size_t)(r0+i)*C + c0 + threadIdx.x];
    __syncthreads();
#pragma unroll
    for(int i=threadIdx.y;i<32;i+=8)
        d[(size_t)(c0+i)*R + r0 + threadIdx.x] = t[threadIdx.x][i];
}

// ------------------------------------------------------------------ embed
__global__ void embed_k(const float* __restrict__ x, const float* __restrict__ w,
                        const float* __restrict__ eb, float* __restrict__ z){
    int d = blockIdx.x*128 + threadIdx.x;
    int n = blockIdx.y, b = blockIdx.z;
    float acc = eb[d];
#pragma unroll
    for(int k=0;k<3;k++){
        int nn = n + k - 1;
        if(nn < 0 || nn >= NN) continue;
        const float* xr = x + ((size_t)b*NN + nn)*TFc;
        const float* wr = w + (size_t)d*21 + k;
#pragma unroll
        for(int c=0;c<TFc;c++) acc += xr[c]*wr[c*3];
    }
    z[((size_t)b*NN + n)*DD + d] = acc;
}

// ------------------------------------------------------------------ freq attention (transposed layout)
// zt, lst: [b, d, n] contiguous rows. DIF FFT (natural in, bit-reversed out).
__global__ void freqatt_k(float* __restrict__ zt, float* __restrict__ lst,
                          int* __restrict__ NKo, int* __restrict__ KFo,
                          float2* __restrict__ KVo){
    __shared__ float2 X[2048];
    __shared__ float2 tw[1024];
    __shared__ float amp2[1025];
    __shared__ float rv[256];
    __shared__ int   ri[256];
    __shared__ int   kept[32];
    __shared__ int   nkept;
    __shared__ float thr_s;

    int d = blockIdx.x, b = blockIdx.y, tid = threadIdx.x;
    float* row = zt + ((size_t)b*DD + d)*NN;

    for(int j=tid;j<1024;j+=256){
        float sa,ca;
        sincosf(-3.14159265358979323846f*(float)j*(1.f/1024.f), &sa, &ca);
        tw[j] = make_float2(ca, sa);
    }
    for(int j=tid;j<2048;j+=256)
        X[j] = make_float2(row[j], 0.f);     // coalesced, natural order
    if(tid==0) nkept = 0;
    __syncthreads();

    // 11 radix-2 DIF stages (stride 1024 -> 1); output bit-reversed
    for(int s=11;s>=1;s--){
        int half = 1 << (s-1);
        int tsh  = 11 - s;
        for(int k=tid;k<1024;k+=256){
            int j  = k & (half-1);
            int i1 = ((k >> (s-1)) << s) | j;
            int i2 = i1 + half;
            float2 w = tw[j << tsh];
            float2 u = X[i1], v = X[i2];
            float dr = u.x - v.x, di = u.y - v.y;
            X[i1] = make_float2(u.x+v.x, u.y+v.y);
            X[i2] = make_float2(dr*w.x - di*w.y, dr*w.y + di*w.x);
        }
        __syncthreads();
    }
    // spectrum bin f lives at X[brev11(f)]
    for(int f=tid;f<=1024;f+=256){
        int rf = (int)(__brev((unsigned)f) >> 21);
        float2 v = X[rf];
        amp2[f] = v.x*v.x + v.y*v.y;
    }
    __syncthreads();

    // 4 argmax rounds -> threshold = 4th largest amp^2
    for(int r=0;r<4;r++){
        float bv = -1.f; int bi = 0;
        for(int f=tid;f<=1024;f+=256){
            float v = amp2[f];
            if(v > bv){ bv = v; bi = f; }
        }
        rv[tid] = bv; ri[tid] = bi;
        __syncthreads();
        for(int st=128;st>0;st>>=1){
            if(tid < st && rv[tid+st] > rv[tid]){ rv[tid]=rv[tid+st]; ri[tid]=ri[tid+st]; }
            __syncthreads();
        }
        if(tid==0){
            if(r < 3){ kept[nkept] = ri[0]; nkept++; amp2[ri[0]] = -2.f; }
            else thr_s = rv[0];
        }
        __syncthreads();
    }
    float thr = thr_s;
    for(int f=tid;f<=1024;f+=256){
        if(amp2[f] >= thr){
            int p = atomicAdd(&nkept, 1);
            if(p < 32) kept[p] = f;
        }
    }
    __syncthreads();
    int nk = min(nkept, 32);
    if(tid == 0){  // deterministic order
        for(int i=1;i<nk;i++){
            int key = kept[i], j = i-1;
            while(j >= 0 && kept[j] > key){ kept[j+1] = kept[j]; j--; }
            kept[j+1] = key;
        }
    }
    __syncthreads();

    // sparse inverse rFFT; write lst row, zt row -= (coalesced)
    float* lrow = lst + ((size_t)b*DD + d)*NN;
    for(int n=tid;n<2048;n+=256){
        float acc = 0.f;
        for(int q=0;q<nk;q++){
            int f = kept[q];
            int rf = (int)(__brev((unsigned)f) >> 21);
            float2 Xf = X[rf];
            float wq = (f==0 || f==1024) ? 1.f : 2.f;
            int ph = (f*n) & 2047;
            float2 t = tw[ph & 1023];
            float sg = (ph & 1024) ? -1.f : 1.f;
            float ca = sg*t.x, sa = -sg*t.y;      // e^{+i*2*pi*ph/2048}
            acc += wq*(Xf.x*ca - Xf.y*sa);
        }
        acc *= (1.f/2048.f);
        lrow[n] = acc;
        row[n] -= acc;
    }

    int ns = min(nk, 16);
    int seq = b*DD + d;
    if(tid==0) NKo[seq] = ns;
    if(tid < ns){
        int f = kept[tid];
        KFo[seq*16 + tid] = f;
        KVo[seq*16 + tid] = X[(int)(__brev((unsigned)f) >> 21)];
    }
}

// ------------------------------------------------------------------ 3xTF32 tensor-core GEMM
// C = A@W^T + bias. A:[M,K] rm, W:[Nn,K] rm. mode 0: store; 1: sigmoid; 2: store and Z -= C.
// CTA 128x128, 8 warps (2x4), warp tile 64x32, k-chunk 32, cp.async double buffer.
#define GSTG 9216   // floats per stage (A 4608 + B 4608), rows padded to 36
__global__ __launch_bounds__(256)
void gemm_tc(const float* __restrict__ A, const float* __restrict__ W,
             const float* __restrict__ bias, float* __restrict__ C,
             float* __restrict__ Z, int M, int Nn, int K, int mode){
    extern __shared__ float sm[];
    int tid = threadIdx.x, lane = tid & 31, wid = tid >> 5;
    int wm = wid & 1, wn = wid >> 1;          // 2 x 4 warps
    int bm = blockIdx.y << 7, bn = blockIdx.x << 7;

    float c[4][4][4];
#pragma unroll
    for(int i=0;i<4;i++)
#pragma unroll
        for(int j=0;j<4;j++)
#pragma unroll
            for(int r=0;r<4;r++) c[i][j][r] = 0.f;

    int lrow = tid >> 3;          // 0..31
    int lc4  = (tid & 7) << 2;    // 0,4,...,28
    const float* Ag = A + (size_t)(bm + lrow)*K + lc4;
    const float* Wg = W + (size_t)(bn + lrow)*K + lc4;
    uint32_t sbase = smem_u32(sm);

    int nch = K >> 5;
    // issue chunk kt into stage st
#define GISSUE(st, k0) do{ \
        uint32_t sA = sbase + (uint32_t)((st)*GSTG)*4u; \
        uint32_t sB = sA + 4608u*4u; \
        const float* ag = Ag + (k0); \
        const float* wg = Wg + (k0); \
        _Pragma("unroll") \
        for(int r_=0;r_<4;r_++){ \
            uint32_t off = (uint32_t)(((lrow + 32*r_)*36 + lc4) << 2); \
            CPA16(sA + off, ag + (size_t)(32*r_)*K); \
            CPA16(sB + off, wg + (size_t)(32*r_)*K); \
        } \
        asm volatile("cp.async.commit_group;" ::: "memory"); \
    }while(0)

    GISSUE(0, 0);
    for(int kt=0;kt<nch;kt++){
        int st = kt & 1;
        if(kt+1 < nch){
            GISSUE(st^1, (kt+1) << 5);
            asm volatile("cp.async.wait_group 1;" ::: "memory");
        }else{
            asm volatile("cp.async.wait_group 0;" ::: "memory");
        }
        __syncthreads();

        const float* As = sm + st*GSTG;
        const float* Bs = As + 4608;
#pragma unroll
        for(int ks=0;ks<4;ks++){
            uint32_t ah[4][4], al[4][4], bh[4][2], bl[4][2];
#pragma unroll
            for(int mt=0;mt<4;mt++){
                int r0 = wm*64 + mt*16 + (lane >> 2);
                int cc = ks*8 + (lane & 3);
                split_tf(As[r0*36 + cc],        ah[mt][0], al[mt][0]);
                split_tf(As[(r0+8)*36 + cc],    ah[mt][1], al[mt][1]);
                split_tf(As[r0*36 + cc + 4],    ah[mt][2], al[mt][2]);
                split_tf(As[(r0+8)*36 + cc + 4],ah[mt][3], al[mt][3]);
            }
#pragma unroll
            for(int nt=0;nt<4;nt++){
                int n0 = wn*32 + nt*8 + (lane >> 2);
                int kk = ks*8 + (lane & 3);
                split_tf(Bs[n0*36 + kk],     bh[nt][0], bl[nt][0]);
                split_tf(Bs[n0*36 + kk + 4], bh[nt][1], bl[nt][1]);
            }
#pragma unroll
            for(int mt=0;mt<4;mt++)
#pragma unroll
                for(int nt=0;nt<4;nt++){
                    mma8(c[mt][nt], ah[mt], bh[nt]);
                    mma8(c[mt][nt], ah[mt], bl[nt]);
                    mma8(c[mt][nt], al[mt], bh[nt]);
                }
        }
        __syncthreads();
    }

    // epilogue
#pragma unroll
    for(int mt=0;mt<4;mt++){
#pragma unroll
        for(int nt=0;nt<4;nt++){
            int row0 = bm + wm*64 + mt*16 + (lane >> 2);
            int col  = bn + wn*32 + nt*8 + 2*(lane & 3);
            float b0 = bias[col], b1 = bias[col+1];
            float v0 = c[mt][nt][0] + b0, v1 = c[mt][nt][1] + b1;
            float v2 = c[mt][nt][2] + b0, v3 = c[mt][nt][3] + b1;
            if(mode == 1){
                v0 = sigm(v0); v1 = sigm(v1); v2 = sigm(v2); v3 = sigm(v3);
            }
            float* c0 = C + (size_t)row0*Nn + col;
            float* c1 = C + (size_t)(row0+8)*Nn + col;
            c0[0] = v0; c0[1] = v1;
            c1[0] = v2; c1[1] = v3;
            if(mode == 2){
                float* z0 = Z + (size_t)row0*Nn + col;
                float* z1 = Z + (size_t)(row0+8)*Nn + col;
                z0[0] -= v0; z0[1] -= v1;
                z1[0] -= v2; z1[1] -= v3;
            }
        }
    }
}

// ------------------------------------------------------------------ mhesa recurrence (in place)
__global__ void mhesa_rec_k(float* __restrict__ h1, const float* __restrict__ alpha_raw,
                            const float* __restrict__ init, int layer){
    int id = blockIdx.x*256 + threadIdx.x;   // 8192
    int b = id >> 9, d = id & 511;
    float al = sigm(alpha_raw[layer*HH + (d>>6)]);
    float om = 1.f - al;
    float ini = init[layer*DD + d];
    float* p = h1 + (size_t)b*NN*DD + d;
    float prev = ini, S = 0.f, pw = om;
    for(int t=0;t<NN;t+=8){
        float v[8];
#pragma unroll
        for(int j=0;j<8;j++) v[j] = p[(size_t)(t+j)*DD];
#pragma unroll
        for(int j=0;j<8;j++){
            float u = v[j] - prev; prev = v[j];
            S = om*S + al*u;
            v[j] = S + pw*ini;
            pw *= om;
        }
#pragma unroll
        for(int j=0;j<8;j++) p[(size_t)(t+j)*DD] = v[j];
    }
}

// ------------------------------------------------------------------ projection from transposed latents
// SP[b,n,f] = sum_d LST[b,d,n]*W[f,d] + bias[f]
__global__ void projT_k(const float* __restrict__ LST, const float* __restrict__ W,
                        const float* __restrict__ bias, float* __restrict__ SP){
    __shared__ float w[TFc][DD];
    int b = blockIdx.y, tid = threadIdx.x;
    int n = (blockIdx.x << 8) + tid;
    for(int i=tid;i<TFc*DD;i+=256) w[i/DD][i%DD] = W[i];
    __syncthreads();
    const float* base = LST + (size_t)b*DD*NN + n;
    float acc[TFc];
#pragma unroll
    for(int f=0;f<TFc;f++) acc[f] = 0.f;
    for(int d=0;d<DD;d++){
        float v = base[(size_t)d*NN];
#pragma unroll
        for(int f=0;f<TFc;f++) acc[f] += w[f][d]*v;
    }
    float* o = SP + ((size_t)b*NN + n)*TFc;
#pragma unroll
    for(int f=0;f<TFc;f++) o[f] = acc[f] + bias[f];
}

// ------------------------------------------------------------------ 7-wide projection (row layout)
__global__ void proj7_k(const float* __restrict__ A, const float* __restrict__ W,
                        const float* __restrict__ bias, float* __restrict__ out){
    int gw = (blockIdx.x*256 + threadIdx.x) >> 5;   // row
    int lane = threadIdx.x & 31;
    if(gw >= BB*NN) return;
    const float* ra = A + (size_t)gw*DD;
    float acc[TFc];
#pragma unroll
    for(int f=0;f<TFc;f++) acc[f] = 0.f;
    for(int k=lane;k<DD;k+=32){
        float a = ra[k];
#pragma unroll
        for(int f=0;f<TFc;f++) acc[f] += a*W[f*DD+k];
    }
#pragma unroll
    for(int f=0;f<TFc;f++)
#pragma unroll
        for(int o=16;o>0;o>>=1) acc[f] += __shfl_xor_sync(0xffffffffu, acc[f], o);
    if(lane==0){
#pragma unroll
        for(int f=0;f<TFc;f++) out[(size_t)gw*TFc + f] = acc[f] + bias[f];
    }
}

// ------------------------------------------------------------------ level recurrences (in place on xl)
__global__ void level_rec_k(float* __restrict__ xl, const float* __restrict__ sp,
                            const float* __restrict__ gp,
                            const float* __restrict__ lv_alpha, int layer){
    int id = threadIdx.x;
    if(id >= BB*TFc) return;
    int b = id / TFc, f = id % TFc;
    float al = sigm(lv_alpha[layer]);
    float om = 1.f - al;
    float t1 = 0.f, t2 = 0.f;
    size_t base = (size_t)b*NN*TFc + f;
    for(int t=0;t<NN;t+=4){
        float xv[4], sv[4], gv[4];
#pragma unroll
        for(int j=0;j<4;j++){
            size_t ix = base + (size_t)(t+j)*TFc;
            xv[j]=xl[ix]; sv[j]=sp[ix]; gv[j]=gp[ix];
        }
#pragma unroll
        for(int j=0;j<4;j++){
            t1 = om*t1 + al*(xv[j]-sv[j]);
            t2 = om*t2 + gv[j];
            xv[j] = t1 + t2;
        }
#pragma unroll
        for(int j=0;j<4;j++) xl[base + (size_t)(t+j)*TFc] = xv[j];
    }
}

// ------------------------------------------------------------------ layer norm
__global__ void ln_k(const float* __restrict__ a, const float* __restrict__ b2,
                     const float* __restrict__ g, const float* __restrict__ bb,
                     float* __restrict__ out){
    __shared__ float v[DD];
    __shared__ float red[256];
    int row = blockIdx.x, tid = threadIdx.x;
    const float* ra = a + (size_t)row*DD;
    const float* rb = b2 ? b2 + (size_t)row*DD : nullptr;
    float s = 0.f;
    for(int i=tid;i<DD;i+=256){
        float x = ra[i] + (rb ? rb[i] : 0.f);
        v[i] = x; s += x;
    }
    red[tid] = s; __syncthreads();
    for(int st=128;st>0;st>>=1){ if(tid<st) red[tid]+=red[tid+st]; __syncthreads(); }
    float mu = red[0] * (1.f/DD);
    __syncthreads();
    s = 0.f;
    for(int i=tid;i<DD;i+=256){ float dd = v[i]-mu; s += dd*dd; }
    red[tid] = s; __syncthreads();
    for(int st=128;st>0;st>>=1){ if(tid<st) red[tid]+=red[tid+st]; __syncthreads(); }
    float inv = 1.f/sqrtf(red[0]*(1.f/DD) + 1e-5f);
    for(int i=tid;i<DD;i+=256)
        out[(size_t)row*DD + i] = (v[i]-mu)*inv*g[i] + bb[i];
}

// ------------------------------------------------------------------ dampening prefix sums
__global__ void pw_k(const float* __restrict__ dampen, float* __restrict__ pw){
    int h = threadIdx.x;
    if(h >= HH) return;
    float df = sigm(dampen[h]);
    float c = 0.f;
    for(int t=0;t<TT;t++){ c += powf(df, (float)(t+1)); pw[t*HH+h] = c; }
}

// ------------------------------------------------------------------ extra + damp  ->  S[b,t,d]
__global__ void extra_damp_k(const float* __restrict__ lastg, const float* __restrict__ pw,
                             const int* __restrict__ NK, const int* __restrict__ KF,
                             const float2* __restrict__ KV, float* __restrict__ S){
    int d = threadIdx.x;
    int t = blockIdx.x, b = blockIdx.y;
    float pwv = pw[t*HH + (d>>6)];
    float tt = (float)(NN + t);
    float acc = 0.f;
#pragma unroll
    for(int l=0;l<2;l++){
        int seq = l*BB*DD + b*DD + d;
        acc += lastg[seq] * pwv;
        int nk = NK[seq];
        float e = 0.f;
        for(int q=0;q<nk;q++){
            int f = KF[seq*16+q];
            float2 X = KV[seq*16+q];
            float sa, ca;
            float ang = ((6.2831855f*(float)f)*tt)*(1.f/2048.f);   // replicate fp32 chain
            sincosf(ang, &sa, &ca);
            e += X.x*ca - X.y*sa;
            if(f != 0 && f != 1024){
                float ang2 = ((6.2831855f*(float)(2048-f))*tt)*(1.f/2048.f);
                sincosf(ang2, &sa, &ca);
                e += X.x*ca + X.y*sa;    // conjugate bin
            }
        }
        acc += e*(1.f/2048.f);
    }
    S[((size_t)b*TT + t)*DD + d] = acc;
}

// ------------------------------------------------------------------ final  out[b,t,f]
__global__ void final_k(const float* __restrict__ S, const float* __restrict__ xl,
                        const float* __restrict__ ltf_w, const float* __restrict__ ltf_b,
                        float* __restrict__ out){
    int id = blockIdx.x*256 + threadIdx.x;
    if(id >= BB*TT*TFc) return;
    int f = id % TFc;
    int t = (id/TFc) % TT;
    int b = id/(TFc*TT);
    const float* sr = S + ((size_t)b*TT + t)*DD;
    const float* wr = ltf_w + (size_t)f*DD;
    float acc = 0.f;
    for(int k=0;k<DD;k++) acc += sr[k]*wr[k];
    out[id] = xl[((size_t)b*NN + (NN-1))*TFc + f] + acc + ltf_b[f];
}

// ------------------------------------------------------------------ launcher
extern "C" void kernel_launch(void* const* d_in, const int* in_sizes, int n_in,
                              void* d_out, int out_size){
    int base = (n_in >= 2 && in_sizes[1] == 1) ? 2 : 1;

    const float* x        = (const float*)d_in[0];
    const float* embed_w  = (const float*)d_in[base+0];
    const float* embed_b  = (const float*)d_in[base+1];
    const float* mh_init  = (const float*)d_in[base+2];
    const float* mh_alpha = (const float*)d_in[base+3];
    const float* pin_w    = (const float*)d_in[base+4];
    const float* pin_b    = (const float*)d_in[base+5];
    const float* pout_w   = (const float*)d_in[base+6];
    const float* pout_b   = (const float*)d_in[base+7];
    const float* n1g      = (const float*)d_in[base+8];
    const float* n1b      = (const float*)d_in[base+9];
    const float* ff1w     = (const float*)d_in[base+10];
    const float* ff1b     = (const float*)d_in[base+11];
    const float* ff2w     = (const float*)d_in[base+12];
    const float* ff2b     = (const float*)d_in[base+13];
    const float* n2g      = (const float*)d_in[base+14];
    const float* n2b      = (const float*)d_in[base+15];
    const float* lv_alpha = (const float*)d_in[base+16];
    const float* tg_w     = (const float*)d_in[base+17];
    const float* tg_b     = (const float*)d_in[base+18];
    const float* ts_w     = (const float*)d_in[base+19];
    const float* ts_b     = (const float*)d_in[base+20];
    const float* dampen   = (const float*)d_in[base+21];
    const float* ltf_w    = (const float*)d_in[base+22];
    const float* ltf_b    = (const float*)d_in[base+23];
    float* out = (float*)d_out;

    float* G = nullptr;
    cudaGetSymbolAddress((void**)&G, g_buf);

    float* Zb  = G;
    float* H1  = G + 1*BND;
    float* LG  = G + 3*BND;
    float* ZN  = G + 4*BND;
    float* FFO = G + 5*BND;
    float* ZT  = G + 6*BND;     // aliases HID (FF intermediate, 4*BND at 6*BND)
    float* LST = G + 7*BND;
    float* HID = G + 6*BND;
    size_t o = 10*BND;
    float* SP    = G + o; o += 229376;
    float* GP    = G + o; o += 229376;
    float* XL    = G + o; o += 229376;
    float* Sb    = G + o; o += 786432;
    float* LASTG = G + o; o += 16384;
    float* PW    = G + o; o += 768;
    int*   NKp   = (int*)(G + o); o += 16384;
    int*   KFp   = (int*)(G + o); o += 262144;
    float2* KVp  = (float2*)(G + o);

    const int GSM = 2*GSTG*4;   // 73728 bytes dynamic smem
    cudaFuncSetAttribute(gemm_tc, cudaFuncAttributeMaxDynamicSharedMemorySize, GSM);

    copy_k<<<896,256>>>(x, XL, BB*NN*TFc);
    embed_k<<<dim3(4,NN,BB),128>>>(x, embed_w, embed_b, Zb);

    for(int l=0;l<2;l++){
        transpose_k<<<dim3(16,64,BB),dim3(32,8)>>>(Zb, ZT, NN, DD);
        freqatt_k<<<dim3(DD,BB),256>>>(ZT, LST, NKp + l*8192, KFp + l*8192*16,
                                       KVp + (size_t)l*8192*16);
        transpose_k<<<dim3(64,16,BB),dim3(32,8)>>>(ZT, Zb, DD, NN);
        projT_k<<<dim3(8,BB),256>>>(LST, ts_w + l*TFc*DD, ts_b + l*TFc, SP);
        gemm_tc<<<dim3(4,256),256,GSM>>>(Zb, pin_w + (size_t)l*DD*DD, pin_b + l*DD,
                                         H1, nullptr, BB*NN, DD, DD, 0);
        mhesa_rec_k<<<32,256>>>(H1, mh_alpha, mh_init, l);
        gemm_tc<<<dim3(4,256),256,GSM>>>(H1, pout_w + (size_t)l*DD*DD, pout_b + l*DD,
                                         LG, Zb, BB*NN, DD, DD, 2);
        copy_lastg_k<<<32,256>>>(LG, LASTG + l*8192);
        proj7_k<<<4096,256>>>(LG, tg_w + l*TFc*DD, tg_b + l*TFc, GP);
        level_rec_k<<<1,128>>>(XL, SP, GP, lv_alpha, l);
        if(l == 0){
            ln_k<<<BB*NN,256>>>(Zb, nullptr, n1g, n1b, ZN);
            gemm_tc<<<dim3(16,256),256,GSM>>>(ZN, ff1w, ff1b, HID, nullptr, BB*NN, 4*DD, DD, 1);
            gemm_tc<<<dim3(4,256),256,GSM>>>(HID, ff2w, ff2b, FFO, nullptr, BB*NN, DD, 4*DD, 0);
            ln_k<<<BB*NN,256>>>(ZN, FFO, n2g, n2b, Zb);
        }
    }

    pw_k<<<1,8>>>(dampen, PW);
    extra_damp_k<<<dim3(TT,BB),512>>>(LASTG, PW, NKp, KFp, KVp, Sb);
    final_k<<<42,256>>>(Sb, XL, ltf_w, ltf_b, out);
}